// round 8
// baseline (speedup 1.0000x reference)
#include <cuda_runtime.h>

// TreeNLLLoss, single fused kernel (R3 skeleton):
//   loss = sum_e edge_pot[e, 16*tc+tp] + sum_e unary[child_e, tc] + unary[root, l_root]
//   out  = -(loss - partition)
// E = 1,000,000 edges, N = 1,000,001 nodes, C = 16.
//
// This round's single change vs the 36.4us best: edge_pot is loaded with
// ld.global.cv (fetch-volatile / no-cache) instead of ld.global.cs.
// Hypothesis: .cv avoids full 128B L2 line allocation+fill for the one-shot
// random element stream (1M x 4B useful out of 1M x 128B line fills = the
// dominant DRAM traffic). If fills become sector-granular, compulsory DRAM
// drops 128MB -> 32MB.

#define C 16
#define EPT 8
#define THREADS 256
#define MAX_BLOCKS 4096

__device__ float    g_partials[MAX_BLOCKS];
__device__ unsigned g_count = 0;   // always returns to 0 (last block resets)

__device__ __forceinline__ float ld_cv(const float* p)
{
    float v;
    asm volatile("ld.global.cv.f32 %0, [%1];" : "=f"(v) : "l"(p));
    return v;
}

__global__ void __launch_bounds__(THREADS)
fused_kernel(const float* __restrict__ edge_pot,
             const float* __restrict__ unary,
             const int*   __restrict__ labels,
             const int*   __restrict__ child_idx,
             const int*   __restrict__ parent_idx,
             const int*   __restrict__ root_idx,
             const float* __restrict__ partition,
             float* __restrict__ out,
             int E)
{
    const int tid  = blockIdx.x * THREADS + threadIdx.x;
    const int base = tid * EPT;

    float s = 0.0f;

    if (base + EPT <= E) {
        // Level 0: vectorized streamed index loads (two int4 per array)
        int4 c4a = __ldg((const int4*)child_idx  + 2 * tid);
        int4 c4b = __ldg((const int4*)child_idx  + 2 * tid + 1);
        int4 p4a = __ldg((const int4*)parent_idx + 2 * tid);
        int4 p4b = __ldg((const int4*)parent_idx + 2 * tid + 1);
        int c[EPT] = {c4a.x, c4a.y, c4a.z, c4a.w, c4b.x, c4b.y, c4b.z, c4b.w};
        int p[EPT] = {p4a.x, p4a.y, p4a.z, p4a.w, p4b.x, p4b.y, p4b.z, p4b.w};

        // Level 1: label gathers (L2-resident, batched -> MLP=16)
        int tc[EPT], tp[EPT];
        #pragma unroll
        for (int j = 0; j < EPT; j++) {
            tc[j] = __ldg(&labels[c[j]]);
            tp[j] = __ldg(&labels[p[j]]);
        }

        // Level 2: potential gathers (batched -> MLP=16)
        //   edge_pot: one-shot stream -> ld.global.cv (no cache allocation)
        //   unary:    reusable -> default nc caching (stays in L2)
        float ep[EPT], cu[EPT];
        #pragma unroll
        for (int j = 0; j < EPT; j++) {
            ep[j] = ld_cv(&edge_pot[(size_t)(base + j) * (C * C) + tc[j] * C + tp[j]]);
            cu[j] = __ldg(&unary[(size_t)c[j] * C + tc[j]]);
        }

        #pragma unroll
        for (int j = 0; j < EPT; j++) s += ep[j] + cu[j];
    } else {
        // tail (unused for E = 1e6, kept for safety)
        for (int j = 0; j < EPT; j++) {
            int e = base + j;
            if (e < E) {
                int ci = __ldg(&child_idx[e]);
                int pi = __ldg(&parent_idx[e]);
                int tc = __ldg(&labels[ci]);
                int tp = __ldg(&labels[pi]);
                s += ld_cv(&edge_pot[(size_t)e * (C * C) + tc * C + tp]);
                s += __ldg(&unary[(size_t)ci * C + tc]);
            }
        }
    }

    // ── block reduce (warp shuffle -> shared -> warp 0) ──
    #pragma unroll
    for (int off = 16; off > 0; off >>= 1)
        s += __shfl_down_sync(0xffffffffu, s, off);

    __shared__ float warp_sums[THREADS / 32];
    const int lane = threadIdx.x & 31;
    const int wid  = threadIdx.x >> 5;
    if (lane == 0) warp_sums[wid] = s;
    __syncthreads();

    if (wid == 0) {
        float t = (lane < THREADS / 32) ? warp_sums[lane] : 0.0f;
        #pragma unroll
        for (int off = 4; off > 0; off >>= 1)
            t += __shfl_down_sync(0xffffffffu, t, off);
        if (lane == 0) g_partials[blockIdx.x] = t;
    }

    // ── last-block-done finalize ──
    __shared__ bool is_last;
    __threadfence();
    if (threadIdx.x == 0) {
        unsigned ticket = atomicAdd(&g_count, 1u);
        is_last = (ticket == gridDim.x - 1);
    }
    __syncthreads();

    if (is_last) {
        double acc = 0.0;
        for (int i = threadIdx.x; i < (int)gridDim.x; i += THREADS)
            acc += (double)__ldcg(&g_partials[i]);

        #pragma unroll
        for (int off = 16; off > 0; off >>= 1)
            acc += __shfl_down_sync(0xffffffffu, acc, off);

        __shared__ double dwarp[THREADS / 32];
        if (lane == 0) dwarp[wid] = acc;
        __syncthreads();

        if (wid == 0) {
            double t = (lane < THREADS / 32) ? dwarp[lane] : 0.0;
            #pragma unroll
            for (int off = 4; off > 0; off >>= 1)
                t += __shfl_down_sync(0xffffffffu, t, off);
            if (lane == 0) {
                int r = __ldg(root_idx);
                float root_unary = __ldg(&unary[(size_t)r * C + __ldg(&labels[r])]);
                double loss = t + (double)root_unary;
                out[0] = -(float)(loss - (double)__ldg(partition));
                g_count = 0;   // reset for next replay
            }
        }
    }
}

extern "C" void kernel_launch(void* const* d_in, const int* in_sizes, int n_in,
                              void* d_out, int out_size)
{
    const float* edge_pot   = (const float*)d_in[0];
    const float* unary      = (const float*)d_in[1];
    const int*   labels     = (const int*)d_in[2];
    const int*   child_idx  = (const int*)d_in[3];
    const int*   parent_idx = (const int*)d_in[4];
    const int*   root_idx   = (const int*)d_in[5];
    const float* partition  = (const float*)d_in[6];
    float* out = (float*)d_out;

    int E = in_sizes[3];

    int per_block = THREADS * EPT;
    int blocks = (E + per_block - 1) / per_block;
    if (blocks > MAX_BLOCKS) blocks = MAX_BLOCKS;  // E=1e6 -> 489

    fused_kernel<<<blocks, THREADS>>>(edge_pot, unary, labels, child_idx,
                                      parent_idx, root_idx, partition, out, E);
}

// round 9
// speedup vs baseline: 1.0468x; 1.0468x over previous
#include <cuda_runtime.h>

// TreeNLLLoss, single fused kernel (R3 skeleton):
//   loss = sum_e edge_pot[e, 16*tc+tp] + sum_e unary[child_e, tc] + unary[root, l_root]
//   out  = -(loss - partition)
// E = 1,000,000 edges, N = 1,000,001 nodes, C = 16.
//
// This round's single change vs the 36.4us best: edge_pot is loaded with
// ld.global.cv (fetch-volatile / no-cache) instead of ld.global.cs.
// Hypothesis: .cv avoids full 128B L2 line allocation+fill for the one-shot
// random element stream (1M x 4B useful out of 1M x 128B line fills = the
// dominant DRAM traffic). If fills become sector-granular, compulsory DRAM
// drops 128MB -> 32MB.

#define C 16
#define EPT 8
#define THREADS 256
#define MAX_BLOCKS 4096

__device__ float    g_partials[MAX_BLOCKS];
__device__ unsigned g_count = 0;   // always returns to 0 (last block resets)

__device__ __forceinline__ float ld_cv(const float* p)
{
    float v;
    asm volatile("ld.global.cv.f32 %0, [%1];" : "=f"(v) : "l"(p));
    return v;
}

__global__ void __launch_bounds__(THREADS)
fused_kernel(const float* __restrict__ edge_pot,
             const float* __restrict__ unary,
             const int*   __restrict__ labels,
             const int*   __restrict__ child_idx,
             const int*   __restrict__ parent_idx,
             const int*   __restrict__ root_idx,
             const float* __restrict__ partition,
             float* __restrict__ out,
             int E)
{
    const int tid  = blockIdx.x * THREADS + threadIdx.x;
    const int base = tid * EPT;

    float s = 0.0f;

    if (base + EPT <= E) {
        // Level 0: vectorized streamed index loads (two int4 per array)
        int4 c4a = __ldg((const int4*)child_idx  + 2 * tid);
        int4 c4b = __ldg((const int4*)child_idx  + 2 * tid + 1);
        int4 p4a = __ldg((const int4*)parent_idx + 2 * tid);
        int4 p4b = __ldg((const int4*)parent_idx + 2 * tid + 1);
        int c[EPT] = {c4a.x, c4a.y, c4a.z, c4a.w, c4b.x, c4b.y, c4b.z, c4b.w};
        int p[EPT] = {p4a.x, p4a.y, p4a.z, p4a.w, p4b.x, p4b.y, p4b.z, p4b.w};

        // Level 1: label gathers (L2-resident, batched -> MLP=16)
        int tc[EPT], tp[EPT];
        #pragma unroll
        for (int j = 0; j < EPT; j++) {
            tc[j] = __ldg(&labels[c[j]]);
            tp[j] = __ldg(&labels[p[j]]);
        }

        // Level 2: potential gathers (batched -> MLP=16)
        //   edge_pot: one-shot stream -> ld.global.cv (no cache allocation)
        //   unary:    reusable -> default nc caching (stays in L2)
        float ep[EPT], cu[EPT];
        #pragma unroll
        for (int j = 0; j < EPT; j++) {
            ep[j] = ld_cv(&edge_pot[(size_t)(base + j) * (C * C) + tc[j] * C + tp[j]]);
            cu[j] = __ldg(&unary[(size_t)c[j] * C + tc[j]]);
        }

        #pragma unroll
        for (int j = 0; j < EPT; j++) s += ep[j] + cu[j];
    } else {
        // tail (unused for E = 1e6, kept for safety)
        for (int j = 0; j < EPT; j++) {
            int e = base + j;
            if (e < E) {
                int ci = __ldg(&child_idx[e]);
                int pi = __ldg(&parent_idx[e]);
                int tc = __ldg(&labels[ci]);
                int tp = __ldg(&labels[pi]);
                s += ld_cv(&edge_pot[(size_t)e * (C * C) + tc * C + tp]);
                s += __ldg(&unary[(size_t)ci * C + tc]);
            }
        }
    }

    // ── block reduce (warp shuffle -> shared -> warp 0) ──
    #pragma unroll
    for (int off = 16; off > 0; off >>= 1)
        s += __shfl_down_sync(0xffffffffu, s, off);

    __shared__ float warp_sums[THREADS / 32];
    const int lane = threadIdx.x & 31;
    const int wid  = threadIdx.x >> 5;
    if (lane == 0) warp_sums[wid] = s;
    __syncthreads();

    if (wid == 0) {
        float t = (lane < THREADS / 32) ? warp_sums[lane] : 0.0f;
        #pragma unroll
        for (int off = 4; off > 0; off >>= 1)
            t += __shfl_down_sync(0xffffffffu, t, off);
        if (lane == 0) g_partials[blockIdx.x] = t;
    }

    // ── last-block-done finalize ──
    __shared__ bool is_last;
    __threadfence();
    if (threadIdx.x == 0) {
        unsigned ticket = atomicAdd(&g_count, 1u);
        is_last = (ticket == gridDim.x - 1);
    }
    __syncthreads();

    if (is_last) {
        double acc = 0.0;
        for (int i = threadIdx.x; i < (int)gridDim.x; i += THREADS)
            acc += (double)__ldcg(&g_partials[i]);

        #pragma unroll
        for (int off = 16; off > 0; off >>= 1)
            acc += __shfl_down_sync(0xffffffffu, acc, off);

        __shared__ double dwarp[THREADS / 32];
        if (lane == 0) dwarp[wid] = acc;
        __syncthreads();

        if (wid == 0) {
            double t = (lane < THREADS / 32) ? dwarp[lane] : 0.0;
            #pragma unroll
            for (int off = 4; off > 0; off >>= 1)
                t += __shfl_down_sync(0xffffffffu, t, off);
            if (lane == 0) {
                int r = __ldg(root_idx);
                float root_unary = __ldg(&unary[(size_t)r * C + __ldg(&labels[r])]);
                double loss = t + (double)root_unary;
                out[0] = -(float)(loss - (double)__ldg(partition));
                g_count = 0;   // reset for next replay
            }
        }
    }
}

extern "C" void kernel_launch(void* const* d_in, const int* in_sizes, int n_in,
                              void* d_out, int out_size)
{
    const float* edge_pot   = (const float*)d_in[0];
    const float* unary      = (const float*)d_in[1];
    const int*   labels     = (const int*)d_in[2];
    const int*   child_idx  = (const int*)d_in[3];
    const int*   parent_idx = (const int*)d_in[4];
    const int*   root_idx   = (const int*)d_in[5];
    const float* partition  = (const float*)d_in[6];
    float* out = (float*)d_out;

    int E = in_sizes[3];

    int per_block = THREADS * EPT;
    int blocks = (E + per_block - 1) / per_block;
    if (blocks > MAX_BLOCKS) blocks = MAX_BLOCKS;  // E=1e6 -> 489

    fused_kernel<<<blocks, THREADS>>>(edge_pot, unary, labels, child_idx,
                                      parent_idx, root_idx, partition, out, E);
}

// round 10
// speedup vs baseline: 1.2179x; 1.1634x over previous
#include <cuda_runtime.h>
#include <cstdint>

// TreeNLLLoss, single fused kernel (R3 skeleton, best=36.4us):
//   loss = sum_e edge_pot[e, 16*tc+tp] + sum_e unary[child_e, tc] + unary[root, l_root]
//   out  = -(loss - partition)
// E = 1,000,000 edges, N = 1,000,001 nodes, C = 16.
//
// Change this round: pin the cross-replay-reusable arrays (unary 64MB,
// labels 4MB, idx 8MB = 76MB < 126MB L2) with L2::evict_last cache policy,
// so the compulsory 128MB/replay edge_pot line stream (ldcs, evict-first)
// cannot displace them. Warm-replay DRAM should drop to ~= the edge stream.

#define C 16
#define EPT 8
#define THREADS 256
#define MAX_BLOCKS 4096

__device__ float    g_partials[MAX_BLOCKS];
__device__ unsigned g_count = 0;   // returns to 0 each replay (last block resets)

// L2 evict_last policy (fraction 1.0)
__device__ __forceinline__ uint64_t make_evict_last_policy()
{
    uint64_t pol;
    asm("createpolicy.fractional.L2::evict_last.b64 %0, 1.0;" : "=l"(pol));
    return pol;
}

__device__ __forceinline__ float ld_pin_f32(const float* p, uint64_t pol)
{
    float v;
    asm("ld.global.nc.L2::cache_hint.f32 %0, [%1], %2;"
        : "=f"(v) : "l"(p), "l"(pol));
    return v;
}

__device__ __forceinline__ int ld_pin_s32(const int* p, uint64_t pol)
{
    int v;
    asm("ld.global.nc.L2::cache_hint.b32 %0, [%1], %2;"
        : "=r"(v) : "l"(p), "l"(pol));
    return v;
}

__device__ __forceinline__ int4 ld_pin_int4(const int4* p, uint64_t pol)
{
    int4 v;
    asm("ld.global.nc.L2::cache_hint.v4.b32 {%0,%1,%2,%3}, [%4], %5;"
        : "=r"(v.x), "=r"(v.y), "=r"(v.z), "=r"(v.w)
        : "l"(p), "l"(pol));
    return v;
}

__global__ void __launch_bounds__(THREADS)
fused_kernel(const float* __restrict__ edge_pot,
             const float* __restrict__ unary,
             const int*   __restrict__ labels,
             const int*   __restrict__ child_idx,
             const int*   __restrict__ parent_idx,
             const int*   __restrict__ root_idx,
             const float* __restrict__ partition,
             float* __restrict__ out,
             int E)
{
    const int tid  = blockIdx.x * THREADS + threadIdx.x;
    const int base = tid * EPT;
    const uint64_t pol = make_evict_last_policy();

    float s = 0.0f;

    if (base + EPT <= E) {
        // Level 0: coalesced index streams (pinned: reused every replay)
        int4 c4a = ld_pin_int4((const int4*)child_idx  + 2 * tid, pol);
        int4 c4b = ld_pin_int4((const int4*)child_idx  + 2 * tid + 1, pol);
        int4 p4a = ld_pin_int4((const int4*)parent_idx + 2 * tid, pol);
        int4 p4b = ld_pin_int4((const int4*)parent_idx + 2 * tid + 1, pol);
        int c[EPT] = {c4a.x, c4a.y, c4a.z, c4a.w, c4b.x, c4b.y, c4b.z, c4b.w};
        int p[EPT] = {p4a.x, p4a.y, p4a.z, p4a.w, p4b.x, p4b.y, p4b.z, p4b.w};

        // Level 1: label gathers (pinned, 4MB)
        int tc[EPT], tp[EPT];
        #pragma unroll
        for (int j = 0; j < EPT; j++) {
            tc[j] = ld_pin_s32(&labels[c[j]], pol);
            tp[j] = ld_pin_s32(&labels[p[j]], pol);
        }

        // Level 2: potential gathers (batched -> MLP=16)
        //   edge_pot: compulsory one-shot line stream -> evict-first
        //   unary:    pinned evict_last (64MB, reused every replay)
        float ep[EPT], cu[EPT];
        #pragma unroll
        for (int j = 0; j < EPT; j++) {
            ep[j] = __ldcs(&edge_pot[(size_t)(base + j) * (C * C) + tc[j] * C + tp[j]]);
            cu[j] = ld_pin_f32(&unary[(size_t)c[j] * C + tc[j]], pol);
        }

        #pragma unroll
        for (int j = 0; j < EPT; j++) s += ep[j] + cu[j];
    } else {
        // tail (unused for E = 1e6, kept for safety)
        for (int j = 0; j < EPT; j++) {
            int e = base + j;
            if (e < E) {
                int ci = __ldg(&child_idx[e]);
                int pi = __ldg(&parent_idx[e]);
                int tc = __ldg(&labels[ci]);
                int tp = __ldg(&labels[pi]);
                s += __ldcs(&edge_pot[(size_t)e * (C * C) + tc * C + tp]);
                s += __ldg(&unary[(size_t)ci * C + tc]);
            }
        }
    }

    // ── block reduce (warp shuffle -> shared -> warp 0) ──
    #pragma unroll
    for (int off = 16; off > 0; off >>= 1)
        s += __shfl_down_sync(0xffffffffu, s, off);

    __shared__ float warp_sums[THREADS / 32];
    const int lane = threadIdx.x & 31;
    const int wid  = threadIdx.x >> 5;
    if (lane == 0) warp_sums[wid] = s;
    __syncthreads();

    if (wid == 0) {
        float t = (lane < THREADS / 32) ? warp_sums[lane] : 0.0f;
        #pragma unroll
        for (int off = 4; off > 0; off >>= 1)
            t += __shfl_down_sync(0xffffffffu, t, off);
        if (lane == 0) g_partials[blockIdx.x] = t;
    }

    // ── last-block-done finalize ──
    __shared__ bool is_last;
    __threadfence();
    if (threadIdx.x == 0) {
        unsigned ticket = atomicAdd(&g_count, 1u);
        is_last = (ticket == gridDim.x - 1);
    }
    __syncthreads();

    if (is_last) {
        double acc = 0.0;
        for (int i = threadIdx.x; i < (int)gridDim.x; i += THREADS)
            acc += (double)__ldcg(&g_partials[i]);

        #pragma unroll
        for (int off = 16; off > 0; off >>= 1)
            acc += __shfl_down_sync(0xffffffffu, acc, off);

        __shared__ double dwarp[THREADS / 32];
        if (lane == 0) dwarp[wid] = acc;
        __syncthreads();

        if (wid == 0) {
            double t = (lane < THREADS / 32) ? dwarp[lane] : 0.0;
            #pragma unroll
            for (int off = 4; off > 0; off >>= 1)
                t += __shfl_down_sync(0xffffffffu, t, off);
            if (lane == 0) {
                int r = __ldg(root_idx);
                float root_unary = __ldg(&unary[(size_t)r * C + __ldg(&labels[r])]);
                double loss = t + (double)root_unary;
                out[0] = -(float)(loss - (double)__ldg(partition));
                g_count = 0;   // reset for next replay
            }
        }
    }
}

extern "C" void kernel_launch(void* const* d_in, const int* in_sizes, int n_in,
                              void* d_out, int out_size)
{
    const float* edge_pot   = (const float*)d_in[0];
    const float* unary      = (const float*)d_in[1];
    const int*   labels     = (const int*)d_in[2];
    const int*   child_idx  = (const int*)d_in[3];
    const int*   parent_idx = (const int*)d_in[4];
    const int*   root_idx   = (const int*)d_in[5];
    const float* partition  = (const float*)d_in[6];
    float* out = (float*)d_out;

    int E = in_sizes[3];

    int per_block = THREADS * EPT;
    int blocks = (E + per_block - 1) / per_block;
    if (blocks > MAX_BLOCKS) blocks = MAX_BLOCKS;  // E=1e6 -> 489

    fused_kernel<<<blocks, THREADS>>>(edge_pot, unary, labels, child_idx,
                                      parent_idx, root_idx, partition, out, E);
}

// round 11
// speedup vs baseline: 1.2390x; 1.0173x over previous
#include <cuda_runtime.h>

// TreeNLLLoss — single kernel, software-pipelined tile sweep.
//   loss = sum_e edge_pot[e,16tc+tp] + sum_e unary[child_e,tc] + unary[root,l_root]
//   out  = -(loss - partition)
// E = 1,000,000, N = 1,000,001, C = 16.
//
// Structure: grid = 2 blocks/SM, each block strides over tiles of
// (THREADS*EPT) edges. 2-deep pipeline: while tile t's 16 random gathers
// (edge_pot via ldcs + unary) are in flight, resolve tile t+1's indices and
// labels and issue t+1's gathers BEFORE accumulating t. Keeps DRAM miss
// queue continuously full instead of burst-drain per short-lived block.

#define C 16
#define EPT 4
#define THREADS 256
#define MAX_BLOCKS 4096

__device__ float    g_partials[MAX_BLOCKS];
__device__ unsigned g_count = 0;   // returns to 0 each replay (last block resets)

struct Tile {
    int   c[EPT];
    float ep[EPT];
    float cu[EPT];
};

// load indices + labels + issue all gathers for tile `t` (t < full_tiles)
__device__ __forceinline__ void issue_tile(
    Tile& T, int t, int thr,
    const float* __restrict__ edge_pot,
    const float* __restrict__ unary,
    const int*   __restrict__ labels,
    const int*   __restrict__ child_idx,
    const int*   __restrict__ parent_idx)
{
    const int vec = t * THREADS + thr;     // int4 slot
    const int base = vec * EPT;

    int4 c4 = __ldg((const int4*)child_idx  + vec);
    int4 p4 = __ldg((const int4*)parent_idx + vec);
    T.c[0] = c4.x; T.c[1] = c4.y; T.c[2] = c4.z; T.c[3] = c4.w;
    int p[EPT] = {p4.x, p4.y, p4.z, p4.w};

    int tc[EPT], tp[EPT];
    #pragma unroll
    for (int j = 0; j < EPT; j++) {
        tc[j] = __ldg(&labels[T.c[j]]);
        tp[j] = __ldg(&labels[p[j]]);
    }

    #pragma unroll
    for (int j = 0; j < EPT; j++)
        T.ep[j] = __ldcs(&edge_pot[(size_t)(base + j) * (C * C) + tc[j] * C + tp[j]]);
    #pragma unroll
    for (int j = 0; j < EPT; j++)
        T.cu[j] = __ldg(&unary[(size_t)T.c[j] * C + tc[j]]);
}

__global__ void __launch_bounds__(THREADS)
fused_kernel(const float* __restrict__ edge_pot,
             const float* __restrict__ unary,
             const int*   __restrict__ labels,
             const int*   __restrict__ child_idx,
             const int*   __restrict__ parent_idx,
             const int*   __restrict__ root_idx,
             const float* __restrict__ partition,
             float* __restrict__ out,
             int E, int full_tiles, int n_blocks)
{
    const int thr = threadIdx.x;
    float s = 0.0f;

    // ── pipelined sweep over full tiles: block b takes tiles b, b+nb, b+2nb… ──
    {
        Tile A, B;
        int t0 = blockIdx.x;
        bool haveA = (t0 < full_tiles);
        if (haveA) issue_tile(A, t0, thr, edge_pot, unary, labels, child_idx, parent_idx);

        int t = t0;
        while (haveA) {
            int t1 = t + n_blocks;
            bool haveB = (t1 < full_tiles);
            if (haveB)
                issue_tile(B, t1, thr, edge_pot, unary, labels, child_idx, parent_idx);

            // consume A (its gathers have been in flight across B's issue)
            #pragma unroll
            for (int j = 0; j < EPT; j++) s += A.ep[j] + A.cu[j];

            A = B;
            t = t1;
            haveA = haveB;
        }
    }

    // ── tail edges (E not multiple of THREADS*EPT) ── handled by block 0
    if (blockIdx.x == 0) {
        int tail_start = full_tiles * THREADS * EPT;
        for (int e = tail_start + thr; e < E; e += THREADS) {
            int ci = __ldg(&child_idx[e]);
            int pi = __ldg(&parent_idx[e]);
            int tc = __ldg(&labels[ci]);
            int tp = __ldg(&labels[pi]);
            s += __ldcs(&edge_pot[(size_t)e * (C * C) + tc * C + tp]);
            s += __ldg(&unary[(size_t)ci * C + tc]);
        }
    }

    // ── block reduce ──
    #pragma unroll
    for (int off = 16; off > 0; off >>= 1)
        s += __shfl_down_sync(0xffffffffu, s, off);

    __shared__ float warp_sums[THREADS / 32];
    const int lane = thr & 31;
    const int wid  = thr >> 5;
    if (lane == 0) warp_sums[wid] = s;
    __syncthreads();

    if (wid == 0) {
        float t = (lane < THREADS / 32) ? warp_sums[lane] : 0.0f;
        #pragma unroll
        for (int off = 4; off > 0; off >>= 1)
            t += __shfl_down_sync(0xffffffffu, t, off);
        if (lane == 0) g_partials[blockIdx.x] = t;
    }

    // ── last-block-done finalize ──
    __shared__ bool is_last;
    __threadfence();
    if (thr == 0) {
        unsigned ticket = atomicAdd(&g_count, 1u);
        is_last = (ticket == gridDim.x - 1);
    }
    __syncthreads();

    if (is_last) {
        double acc = 0.0;
        for (int i = thr; i < (int)gridDim.x; i += THREADS)
            acc += (double)__ldcg(&g_partials[i]);

        #pragma unroll
        for (int off = 16; off > 0; off >>= 1)
            acc += __shfl_down_sync(0xffffffffu, acc, off);

        __shared__ double dwarp[THREADS / 32];
        if (lane == 0) dwarp[wid] = acc;
        __syncthreads();

        if (wid == 0) {
            double t = (lane < THREADS / 32) ? dwarp[lane] : 0.0;
            #pragma unroll
            for (int off = 4; off > 0; off >>= 1)
                t += __shfl_down_sync(0xffffffffu, t, off);
            if (lane == 0) {
                int r = __ldg(root_idx);
                float root_unary = __ldg(&unary[(size_t)r * C + __ldg(&labels[r])]);
                double loss = t + (double)root_unary;
                out[0] = -(float)(loss - (double)__ldg(partition));
                g_count = 0;   // reset for next replay
            }
        }
    }
}

extern "C" void kernel_launch(void* const* d_in, const int* in_sizes, int n_in,
                              void* d_out, int out_size)
{
    const float* edge_pot   = (const float*)d_in[0];
    const float* unary      = (const float*)d_in[1];
    const int*   labels     = (const int*)d_in[2];
    const int*   child_idx  = (const int*)d_in[3];
    const int*   parent_idx = (const int*)d_in[4];
    const int*   root_idx   = (const int*)d_in[5];
    const float* partition  = (const float*)d_in[6];
    float* out = (float*)d_out;

    int E = in_sizes[3];

    const int SMS = 148;
    int n_blocks = 2 * SMS;                       // 296 — 2 blocks/SM, 1 wave
    if (n_blocks > MAX_BLOCKS) n_blocks = MAX_BLOCKS;

    int per_tile   = THREADS * EPT;               // 1024 edges
    int full_tiles = E / per_tile;                // 976 full tiles (+576 tail)

    fused_kernel<<<n_blocks, THREADS>>>(edge_pot, unary, labels, child_idx,
                                        parent_idx, root_idx, partition, out,
                                        E, full_tiles, n_blocks);
}